// round 12
// baseline (speedup 1.0000x reference)
#include <cuda_runtime.h>
#include <cstdint>

// ----------------------------------------------------------------------------
// TitleGenerator fused kernel, round 8: occupancy attack.
// 148 CTAs x 960 threads (30 warps, was 19 -> latency-bound at issue=28%).
//  threads 0..703  : split-K. row = t>>1 (0..351), K-half = t&1 (64 k each).
//                    lane pairs (2r, 2r+1) reduce via shfl_xor(1).
//                    rows 0..319 weights SMEM-resident; 320..351 streamed.
//  threads 704..959: full-K rows 352..607, weights streamed from L2 with
//                    4-deep prefetch (8 warps, spread across SMSPs).
// Same math as R6/R7 (combined weights exploiting x==h after step 1),
// period-2 bitwise fixed-point detection.
// ----------------------------------------------------------------------------

#define BB      2048
#define HH      128
#define CC      96
#define TSTEPS  400
#define NT      960
#define NWS     320                   // weight rows resident in SMEM
#define TITLES_ELEMS 78643200         // 2048*400*96

// dynamic smem layout (bytes)
#define OFF_W    0
#define SZ_W     (32 * NWS * 16)               // 163840
#define OFF_XH   (OFF_W + SZ_W)                // 163840
#define OFF_XL   (OFF_XH + 14 * 128 * 4)       // 171008
#define OFF_X2   (OFF_XL + 14 * 128 * 4)       // 178176
#define OFF_GSM  (OFF_X2 + 14 * 128 * 4)       // 185344
#define SZ_GSM   (14 * 608 * 4)                // 34048
#define OFF_M4   (OFF_GSM + SZ_GSM)            // 219392
#define OFF_LEN  (OFF_M4 + 256)                // 219648
#define SMEM_TOT (OFF_LEN + 64)                // 219712

typedef unsigned long long ull;

__device__ __forceinline__ void upk2(ull v, float& lo, float& hi) {
    asm("mov.b64 {%0, %1}, %2;" : "=f"(lo), "=f"(hi) : "l"(v));
}
#define FMA2(acc, a, b) asm("fma.rn.f32x2 %0, %1, %2, %3;" : "=l"(acc) : "l"(a), "l"(b), "l"(acc))

__global__ __launch_bounds__(960, 1)
void fused_kernel(float* __restrict__ out,
                  const float* __restrict__ img,
                  const float* __restrict__ lin1_w,
                  const float* __restrict__ lin1_b,
                  const float* __restrict__ w_ih,
                  const float* __restrict__ w_hh,
                  const float* __restrict__ b_ih,
                  const float* __restrict__ b_hh,
                  const float* __restrict__ lin2_w,
                  const float* __restrict__ lin2_b,
                  int hasLens) {
    extern __shared__ __align__(16) char smraw[];
    float4* wsm4 = reinterpret_cast<float4*>(smraw + OFF_W);
    float*  xh   = reinterpret_cast<float*>(smraw + OFF_XH);
    float*  xl   = reinterpret_cast<float*>(smraw + OFF_XL);
    float*  xp2  = reinterpret_cast<float*>(smraw + OFF_X2);
    float*  gsm  = reinterpret_cast<float*>(smraw + OFF_GSM);
    float*  m4   = reinterpret_cast<float*>(smraw + OFF_M4);
    int*    lensm= reinterpret_cast<int*>(smraw + OFF_LEN);

    const int tid = threadIdx.x;
    const int bid = blockIdx.x;
    int base, nv;
    if (bid < 124) { base = bid * 14; nv = 14; }
    else           { base = 1736 + (bid - 124) * 13; nv = 13; }

    const bool isSplit = (tid < 704);
    const int  row  = isSplit ? (tid >> 1) : (tid - 352);   // output row
    const int  half = tid & 1;                              // split threads only
    const int  g0   = half << 4;                            // first granule (split)

    // combined bias for this row
    float bias;
    if (row < 256)      bias = b_ih[row] + b_hh[row];
    else if (row < 384) bias = b_ih[row];
    else if (row < 512) bias = b_hh[row - 128];
    else                bias = lin2_b[row - 512];

    // ---- fill SMEM weights rows [0,NWS), layout [g][row] --------------------
    {
        const float4* wih4 = reinterpret_cast<const float4*>(w_ih);
        const float4* whh4 = reinterpret_cast<const float4*>(w_hh);
        for (int idx = tid; idx < 32 * NWS; idx += NT) {
            int g = idx / NWS;
            int r = idx - g * NWS;
            float4 a = wih4[r * 32 + g];
            if (r < 256) {
                float4 b = whh4[r * 32 + g];
                a.x += b.x; a.y += b.y; a.z += b.z; a.w += b.w;
            }
            wsm4[idx] = a;
        }
    }

    // zero x buffers, lens
    for (int m = tid; m < 14 * 128; m += NT) { xh[m] = 0.f; xl[m] = 0.f; xp2[m] = 0.f; }
    if (tid < 16) lensm[tid] = 0;

    // ---- Phase A: lin1 -> ht rows for this CTA (staged in gsm) --------------
    {
        const int j  = tid & 127;
        const int ks = tid >> 7;          // 0..3 for tid<512
        ull acc[14];
#pragma unroll
        for (int r = 0; r < 14; r++) acc[r] = 0ull;

        float4*       xs4 = reinterpret_cast<float4*>(gsm);
        const float4* im4 = reinterpret_cast<const float4*>(img);
        const ulonglong2* xs2 = reinterpret_cast<const ulonglong2*>(gsm);

        for (int kc = 0; kc < 16; kc++) {
            __syncthreads();
            for (int m = tid; m < 14 * 64; m += NT) {
                int r = m >> 6, kk4 = m & 63;
                float4 v = make_float4(0.f, 0.f, 0.f, 0.f);
                if (r < nv) v = im4[(size_t)(base + r) * 1024 + kc * 64 + kk4];
                xs4[r * 64 + kk4] = v;
            }
            __syncthreads();
            if (tid < 512) {
                const ulonglong2* wl = reinterpret_cast<const ulonglong2*>(
                    lin1_w + (size_t)j * 4096 + kc * 256 + ks * 64);
#pragma unroll 4
                for (int q = 0; q < 16; q++) {
                    ulonglong2 wv = wl[q];
#pragma unroll
                    for (int r = 0; r < 14; r++) {
                        ulonglong2 xv = xs2[r * 64 + ks * 16 + q];
                        FMA2(acc[r], wv.x, xv.x);
                        FMA2(acc[r], wv.y, xv.y);
                    }
                }
            }
        }
        __syncthreads();
        if (tid < 512) {
#pragma unroll
            for (int r = 0; r < 14; r++) {
                float lo, hi; upk2(acc[r], lo, hi);
                gsm[r * 512 + ks * 128 + j] = lo + hi;
            }
        }
        __syncthreads();
        for (int m = tid; m < 14 * 128; m += NT) {
            int r = m >> 7, jj = m & 127;
            float v = gsm[r * 512 + jj] + gsm[r * 512 + 128 + jj]
                    + gsm[r * 512 + 256 + jj] + gsm[r * 512 + 384 + jj] + lin1_b[jj];
            xh[r * 128 + jj] = (v >= 0.f) ? v : 0.01f * v;
        }
        __syncthreads();
    }

    // x source: rows < 512 read h; rows >= 512 (lin2) read leaky(h).
    // Warp-clean: threads 0..863 -> xh, 864..959 -> xl.
    const ulonglong2* xs = (row < 512) ? reinterpret_cast<const ulonglong2*>(xh)
                                       : reinterpret_cast<const ulonglong2*>(xl);
    const ulonglong2* wsm2 = reinterpret_cast<const ulonglong2*>(wsm4);

    // streamed weight pointer
    const ulonglong2* wg = nullptr;
    if (isSplit) {
        if (row >= NWS)   // rows 320..351 are w_ih rows
            wg = reinterpret_cast<const ulonglong2*>(w_ih + (size_t)row * 128 + half * 64);
    } else {
        const float* p;
        if (row < 384)      p = w_ih  + (size_t)row * 128;
        else if (row < 512) p = w_hh  + (size_t)(row - 128) * 128;
        else                p = lin2_w + (size_t)(row - 512) * 128;
        wg = reinterpret_cast<const ulonglong2*>(p);
    }

    // ---- steady-state matvec ------------------------------------------------
    auto matvec = [&]() {
        if (isSplit) {
            ull acc[14];
#pragma unroll
            for (int r = 0; r < 14; r++) acc[r] = 0ull;
            if (row < NWS) {
#pragma unroll 4
                for (int g16 = 0; g16 < 16; g16++) {
                    ulonglong2 w = wsm2[(g0 + g16) * NWS + row];
#pragma unroll
                    for (int r = 0; r < 14; r++) {
                        ulonglong2 xv = xs[r * 32 + g0 + g16];
                        FMA2(acc[r], w.x, xv.x);
                        FMA2(acc[r], w.y, xv.y);
                    }
                }
            } else {
                ulonglong2 cn0 = wg[0], cn1 = wg[1];
#pragma unroll 1
                for (int blk = 0; blk < 8; blk++) {
                    ulonglong2 c0 = cn0, c1 = cn1;
                    if (blk < 7) { cn0 = wg[blk * 2 + 2]; cn1 = wg[blk * 2 + 3]; }
#pragma unroll
                    for (int r = 0; r < 14; r++) {
                        ulonglong2 xv = xs[r * 32 + g0 + blk * 2];
                        FMA2(acc[r], c0.x, xv.x);
                        FMA2(acc[r], c0.y, xv.y);
                    }
#pragma unroll
                    for (int r = 0; r < 14; r++) {
                        ulonglong2 xv = xs[r * 32 + g0 + blk * 2 + 1];
                        FMA2(acc[r], c1.x, xv.x);
                        FMA2(acc[r], c1.y, xv.y);
                    }
                }
            }
#pragma unroll
            for (int r = 0; r < 14; r++) {
                float lo, hi; upk2(acc[r], lo, hi);
                float part = lo + hi;
                part += __shfl_xor_sync(0xffffffffu, part, 1);
                if (half == 0) gsm[r * 608 + row] = part + bias;
            }
        } else {
            ull acc[14];
#pragma unroll
            for (int r = 0; r < 14; r++) acc[r] = 0ull;
            ulonglong2 bn[4];
#pragma unroll
            for (int q = 0; q < 4; q++) bn[q] = wg[q];
#pragma unroll 1
            for (int blk = 0; blk < 8; blk++) {
                ulonglong2 b[4];
#pragma unroll
                for (int q = 0; q < 4; q++) b[q] = bn[q];
                if (blk < 7) {
#pragma unroll
                    for (int q = 0; q < 4; q++) bn[q] = wg[blk * 4 + 4 + q];
                }
#pragma unroll
                for (int q = 0; q < 4; q++) {
#pragma unroll
                    for (int r = 0; r < 14; r++) {
                        ulonglong2 xv = xs[r * 32 + blk * 4 + q];
                        FMA2(acc[r], b[q].x, xv.x);
                        FMA2(acc[r], b[q].y, xv.y);
                    }
                }
            }
#pragma unroll
            for (int r = 0; r < 14; r++) {
                float lo, hi; upk2(acc[r], lo, hi);
                gsm[r * 608 + row] = lo + hi + bias;
            }
        }
    };

    // ---- step-1 matvec: x = ht, h = 0; gate rows (<384) use raw w_ih --------
    auto matvec1 = [&]() {
        const ulonglong2* xg = reinterpret_cast<const ulonglong2*>(xh);
        if (isSplit) {
            // all split rows < 352 < 384: active
            const ulonglong2* w1 = reinterpret_cast<const ulonglong2*>(
                w_ih + (size_t)row * 128 + half * 64);
            ull acc[14];
#pragma unroll
            for (int r = 0; r < 14; r++) acc[r] = 0ull;
#pragma unroll 2
            for (int g16 = 0; g16 < 16; g16++) {
                ulonglong2 w = w1[g16];
#pragma unroll
                for (int r = 0; r < 14; r++) {
                    ulonglong2 xv = xg[r * 32 + g0 + g16];
                    FMA2(acc[r], w.x, xv.x);
                    FMA2(acc[r], w.y, xv.y);
                }
            }
#pragma unroll
            for (int r = 0; r < 14; r++) {
                float lo, hi; upk2(acc[r], lo, hi);
                float part = lo + hi;
                part += __shfl_xor_sync(0xffffffffu, part, 1);
                if (half == 0) gsm[r * 608 + row] = part + bias;
            }
        } else {
            ull acc[14];
#pragma unroll
            for (int r = 0; r < 14; r++) acc[r] = 0ull;
            if (row < 384) {
                const ulonglong2* w1 = reinterpret_cast<const ulonglong2*>(
                    w_ih + (size_t)row * 128);
#pragma unroll 2
                for (int g = 0; g < 32; g++) {
                    ulonglong2 w = w1[g];
#pragma unroll
                    for (int r = 0; r < 14; r++) {
                        ulonglong2 xv = xg[r * 32 + g];
                        FMA2(acc[r], w.x, xv.x);
                        FMA2(acc[r], w.y, xv.y);
                    }
                }
            }
#pragma unroll
            for (int r = 0; r < 14; r++) {
                float lo, hi; upk2(acc[r], lo, hi);
                gsm[r * 608 + row] = lo + hi + bias;
            }
        }
    };

    // ---- GRU gates + state rotation + per-row char maxima -------------------
    auto gatephase = [&](bool step1) -> bool {
        bool changed = false;
        for (int m = tid; m < 14 * HH; m += NT) {
            int r = m >> 7, k = m & 127;
            if (r < nv) {
                float rpre = gsm[r * 608 + k];
                float zpre = gsm[r * 608 + 128 + k];
                float inp  = gsm[r * 608 + 256 + k];
                float hnp  = gsm[r * 608 + 384 + k];
                float rg = __fdividef(1.0f, 1.0f + __expf(-rpre));
                float zg = __fdividef(1.0f, 1.0f + __expf(-zpre));
                float n  = tanhf(inp + rg * hnp);
                int   xi = r * 128 + k;
                float xold = xh[xi];
                float old2 = xp2[xi];
                float hn = step1 ? (1.0f - zg) * n
                                 : (1.0f - zg) * n + zg * xold;
                changed |= (__float_as_int(hn) != __float_as_int(old2));
                xp2[xi] = xold;
                xh[xi]  = hn;
                xl[xi]  = (hn >= 0.f) ? hn : 0.01f * hn;
            }
        }
        if (tid < 56) {
            int r = tid >> 2, q = tid & 3;
            float mx = -3.4e38f;
#pragma unroll
            for (int c = 0; c < 24; c++) mx = fmaxf(mx, gsm[r * 608 + 512 + q * 24 + c]);
            m4[tid] = mx;
        }
        return changed;
    };

    const float THR = (float)(1.0 - 1e-05);

    // pre-step: hn0 = GRU(ht, 0)
    matvec1();
    __syncthreads();
    gatephase(true);
    __syncthreads();

    float cval[2], pval[2];
    int   foff[2];
    int   nslots = 0;
    int   sConv = -1;

    for (int s = 0; s < TSTEPS; s++) {
        matvec();
        __syncthreads();
        bool changed = gatephase(false);
        if (s == 0) changed = true;               // xp2 invalid at s=0
        int cnt = __syncthreads_count(changed ? 1 : 0);

#pragma unroll
        for (int q = 0; q < 2; q++) pval[q] = cval[q];
        nslots = 0;
        for (int m = tid; m < nv * CC; m += NT) {
            int r = m / CC, c = m - r * CC;
            float mx = fmaxf(fmaxf(m4[r * 4 + 0], m4[r * 4 + 1]),
                             fmaxf(m4[r * 4 + 2], m4[r * 4 + 3]));
            float ch = gsm[r * 608 + 512 + c];
            float cn = __fdiv_rn(ch, mx);
            float val = (cn > THR) ? cn : 0.f;
            int off = (base + r) * (TSTEPS * CC) + c;
            out[(size_t)off + (size_t)s * CC] = val;
            if (c == 52 && val == 1.0f && lensm[r] == 0) lensm[r] = s + 1;
            cval[nslots] = val;
            foff[nslots] = off;
            nslots++;
        }

        if (cnt == 0) { sConv = s; break; }
        __syncthreads();
    }

    if (sConv >= 0) {
        // period-2 limit cycle: outputs alternate between steps sConv-1, sConv
        for (int s2 = sConv + 1; s2 < TSTEPS; s2++) {
            bool even = (((s2 - sConv) & 1) == 0);
#pragma unroll
            for (int q = 0; q < 2; q++) {
                if (q < nslots)
                    out[(size_t)foff[q] + (size_t)s2 * CC] = even ? cval[q] : pval[q];
            }
        }
    }

    __syncthreads();
    if (hasLens && tid < nv) {
        int L = lensm[tid];
        out[(size_t)TITLES_ELEMS + base + tid] = (float)(L == 0 ? TSTEPS : L);
    }
}

// ------------------------------- launch -------------------------------------
extern "C" void kernel_launch(void* const* d_in, const int* in_sizes, int n_in,
                              void* d_out, int out_size) {
    const float* img_feat = (const float*)d_in[0];
    const float* lin1_w   = (const float*)d_in[1];
    const float* lin1_b   = (const float*)d_in[2];
    const float* w_ih     = (const float*)d_in[3];
    const float* w_hh     = (const float*)d_in[4];
    const float* b_ih     = (const float*)d_in[5];
    const float* b_hh     = (const float*)d_in[6];
    const float* lin2_w   = (const float*)d_in[7];
    const float* lin2_b   = (const float*)d_in[8];

    cudaFuncSetAttribute(fused_kernel,
                         cudaFuncAttributeMaxDynamicSharedMemorySize, SMEM_TOT);

    int hasLens = (out_size >= TITLES_ELEMS + BB) ? 1 : 0;
    fused_kernel<<<148, 960, SMEM_TOT>>>((float*)d_out, img_feat, lin1_w, lin1_b,
                                         w_ih, w_hh, b_ih, b_hh, lin2_w, lin2_b,
                                         hasLens);
}

// round 13
// speedup vs baseline: 1.6090x; 1.6090x over previous
#include <cuda_runtime.h>
#include <cstdint>

// ----------------------------------------------------------------------------
// TitleGenerator fused kernel, round 8: occupancy attack.
// 148 CTAs x 960 threads (30 warps, was 19 -> latency-bound at issue=28%).
//  threads 0..703  : split-K. row = t>>1 (0..351), K-half = t&1 (64 k each).
//                    lane pairs (2r, 2r+1) reduce via shfl_xor(1).
//                    rows 0..319 weights SMEM-resident; 320..351 streamed.
//  threads 704..959: full-K rows 352..607, weights streamed from L2 with
//                    4-deep prefetch (8 warps, spread across SMSPs).
// Same math as R6/R7 (combined weights exploiting x==h after step 1),
// period-2 bitwise fixed-point detection.
// ----------------------------------------------------------------------------

#define BB      2048
#define HH      128
#define CC      96
#define TSTEPS  400
#define NT      960
#define NWS     320                   // weight rows resident in SMEM
#define TITLES_ELEMS 78643200         // 2048*400*96

// dynamic smem layout (bytes)
#define OFF_W    0
#define SZ_W     (32 * NWS * 16)               // 163840
#define OFF_XH   (OFF_W + SZ_W)                // 163840
#define OFF_XL   (OFF_XH + 14 * 128 * 4)       // 171008
#define OFF_X2   (OFF_XL + 14 * 128 * 4)       // 178176
#define OFF_GSM  (OFF_X2 + 14 * 128 * 4)       // 185344
#define SZ_GSM   (14 * 608 * 4)                // 34048
#define OFF_M4   (OFF_GSM + SZ_GSM)            // 219392
#define OFF_LEN  (OFF_M4 + 256)                // 219648
#define SMEM_TOT (OFF_LEN + 64)                // 219712

typedef unsigned long long ull;

__device__ __forceinline__ void upk2(ull v, float& lo, float& hi) {
    asm("mov.b64 {%0, %1}, %2;" : "=f"(lo), "=f"(hi) : "l"(v));
}
#define FMA2(acc, a, b) asm("fma.rn.f32x2 %0, %1, %2, %3;" : "=l"(acc) : "l"(a), "l"(b), "l"(acc))

__global__ __launch_bounds__(960, 1)
void fused_kernel(float* __restrict__ out,
                  const float* __restrict__ img,
                  const float* __restrict__ lin1_w,
                  const float* __restrict__ lin1_b,
                  const float* __restrict__ w_ih,
                  const float* __restrict__ w_hh,
                  const float* __restrict__ b_ih,
                  const float* __restrict__ b_hh,
                  const float* __restrict__ lin2_w,
                  const float* __restrict__ lin2_b,
                  int hasLens) {
    extern __shared__ __align__(16) char smraw[];
    float4* wsm4 = reinterpret_cast<float4*>(smraw + OFF_W);
    float*  xh   = reinterpret_cast<float*>(smraw + OFF_XH);
    float*  xl   = reinterpret_cast<float*>(smraw + OFF_XL);
    float*  xp2  = reinterpret_cast<float*>(smraw + OFF_X2);
    float*  gsm  = reinterpret_cast<float*>(smraw + OFF_GSM);
    float*  m4   = reinterpret_cast<float*>(smraw + OFF_M4);
    int*    lensm= reinterpret_cast<int*>(smraw + OFF_LEN);

    const int tid = threadIdx.x;
    const int bid = blockIdx.x;
    int base, nv;
    if (bid < 124) { base = bid * 14; nv = 14; }
    else           { base = 1736 + (bid - 124) * 13; nv = 13; }

    const bool isSplit = (tid < 704);
    const int  row  = isSplit ? (tid >> 1) : (tid - 352);   // output row
    const int  half = tid & 1;                              // split threads only
    const int  g0   = half << 4;                            // first granule (split)

    // combined bias for this row
    float bias;
    if (row < 256)      bias = b_ih[row] + b_hh[row];
    else if (row < 384) bias = b_ih[row];
    else if (row < 512) bias = b_hh[row - 128];
    else                bias = lin2_b[row - 512];

    // ---- fill SMEM weights rows [0,NWS), layout [g][row] --------------------
    {
        const float4* wih4 = reinterpret_cast<const float4*>(w_ih);
        const float4* whh4 = reinterpret_cast<const float4*>(w_hh);
        for (int idx = tid; idx < 32 * NWS; idx += NT) {
            int g = idx / NWS;
            int r = idx - g * NWS;
            float4 a = wih4[r * 32 + g];
            if (r < 256) {
                float4 b = whh4[r * 32 + g];
                a.x += b.x; a.y += b.y; a.z += b.z; a.w += b.w;
            }
            wsm4[idx] = a;
        }
    }

    // zero x buffers, lens
    for (int m = tid; m < 14 * 128; m += NT) { xh[m] = 0.f; xl[m] = 0.f; xp2[m] = 0.f; }
    if (tid < 16) lensm[tid] = 0;

    // ---- Phase A: lin1 -> ht rows for this CTA (staged in gsm) --------------
    {
        const int j  = tid & 127;
        const int ks = tid >> 7;          // 0..3 for tid<512
        ull acc[14];
#pragma unroll
        for (int r = 0; r < 14; r++) acc[r] = 0ull;

        float4*       xs4 = reinterpret_cast<float4*>(gsm);
        const float4* im4 = reinterpret_cast<const float4*>(img);
        const ulonglong2* xs2 = reinterpret_cast<const ulonglong2*>(gsm);

        for (int kc = 0; kc < 16; kc++) {
            __syncthreads();
            for (int m = tid; m < 14 * 64; m += NT) {
                int r = m >> 6, kk4 = m & 63;
                float4 v = make_float4(0.f, 0.f, 0.f, 0.f);
                if (r < nv) v = im4[(size_t)(base + r) * 1024 + kc * 64 + kk4];
                xs4[r * 64 + kk4] = v;
            }
            __syncthreads();
            if (tid < 512) {
                const ulonglong2* wl = reinterpret_cast<const ulonglong2*>(
                    lin1_w + (size_t)j * 4096 + kc * 256 + ks * 64);
#pragma unroll 4
                for (int q = 0; q < 16; q++) {
                    ulonglong2 wv = wl[q];
#pragma unroll
                    for (int r = 0; r < 14; r++) {
                        ulonglong2 xv = xs2[r * 64 + ks * 16 + q];
                        FMA2(acc[r], wv.x, xv.x);
                        FMA2(acc[r], wv.y, xv.y);
                    }
                }
            }
        }
        __syncthreads();
        if (tid < 512) {
#pragma unroll
            for (int r = 0; r < 14; r++) {
                float lo, hi; upk2(acc[r], lo, hi);
                gsm[r * 512 + ks * 128 + j] = lo + hi;
            }
        }
        __syncthreads();
        for (int m = tid; m < 14 * 128; m += NT) {
            int r = m >> 7, jj = m & 127;
            float v = gsm[r * 512 + jj] + gsm[r * 512 + 128 + jj]
                    + gsm[r * 512 + 256 + jj] + gsm[r * 512 + 384 + jj] + lin1_b[jj];
            xh[r * 128 + jj] = (v >= 0.f) ? v : 0.01f * v;
        }
        __syncthreads();
    }

    // x source: rows < 512 read h; rows >= 512 (lin2) read leaky(h).
    // Warp-clean: threads 0..863 -> xh, 864..959 -> xl.
    const ulonglong2* xs = (row < 512) ? reinterpret_cast<const ulonglong2*>(xh)
                                       : reinterpret_cast<const ulonglong2*>(xl);
    const ulonglong2* wsm2 = reinterpret_cast<const ulonglong2*>(wsm4);

    // streamed weight pointer
    const ulonglong2* wg = nullptr;
    if (isSplit) {
        if (row >= NWS)   // rows 320..351 are w_ih rows
            wg = reinterpret_cast<const ulonglong2*>(w_ih + (size_t)row * 128 + half * 64);
    } else {
        const float* p;
        if (row < 384)      p = w_ih  + (size_t)row * 128;
        else if (row < 512) p = w_hh  + (size_t)(row - 128) * 128;
        else                p = lin2_w + (size_t)(row - 512) * 128;
        wg = reinterpret_cast<const ulonglong2*>(p);
    }

    // ---- steady-state matvec ------------------------------------------------
    auto matvec = [&]() {
        if (isSplit) {
            ull acc[14];
#pragma unroll
            for (int r = 0; r < 14; r++) acc[r] = 0ull;
            if (row < NWS) {
#pragma unroll 4
                for (int g16 = 0; g16 < 16; g16++) {
                    ulonglong2 w = wsm2[(g0 + g16) * NWS + row];
#pragma unroll
                    for (int r = 0; r < 14; r++) {
                        ulonglong2 xv = xs[r * 32 + g0 + g16];
                        FMA2(acc[r], w.x, xv.x);
                        FMA2(acc[r], w.y, xv.y);
                    }
                }
            } else {
                ulonglong2 cn0 = wg[0], cn1 = wg[1];
#pragma unroll 1
                for (int blk = 0; blk < 8; blk++) {
                    ulonglong2 c0 = cn0, c1 = cn1;
                    if (blk < 7) { cn0 = wg[blk * 2 + 2]; cn1 = wg[blk * 2 + 3]; }
#pragma unroll
                    for (int r = 0; r < 14; r++) {
                        ulonglong2 xv = xs[r * 32 + g0 + blk * 2];
                        FMA2(acc[r], c0.x, xv.x);
                        FMA2(acc[r], c0.y, xv.y);
                    }
#pragma unroll
                    for (int r = 0; r < 14; r++) {
                        ulonglong2 xv = xs[r * 32 + g0 + blk * 2 + 1];
                        FMA2(acc[r], c1.x, xv.x);
                        FMA2(acc[r], c1.y, xv.y);
                    }
                }
            }
#pragma unroll
            for (int r = 0; r < 14; r++) {
                float lo, hi; upk2(acc[r], lo, hi);
                float part = lo + hi;
                part += __shfl_xor_sync(0xffffffffu, part, 1);
                if (half == 0) gsm[r * 608 + row] = part + bias;
            }
        } else {
            ull acc[14];
#pragma unroll
            for (int r = 0; r < 14; r++) acc[r] = 0ull;
            ulonglong2 bn[4];
#pragma unroll
            for (int q = 0; q < 4; q++) bn[q] = wg[q];
#pragma unroll 1
            for (int blk = 0; blk < 8; blk++) {
                ulonglong2 b[4];
#pragma unroll
                for (int q = 0; q < 4; q++) b[q] = bn[q];
                if (blk < 7) {
#pragma unroll
                    for (int q = 0; q < 4; q++) bn[q] = wg[blk * 4 + 4 + q];
                }
#pragma unroll
                for (int q = 0; q < 4; q++) {
#pragma unroll
                    for (int r = 0; r < 14; r++) {
                        ulonglong2 xv = xs[r * 32 + blk * 4 + q];
                        FMA2(acc[r], b[q].x, xv.x);
                        FMA2(acc[r], b[q].y, xv.y);
                    }
                }
            }
#pragma unroll
            for (int r = 0; r < 14; r++) {
                float lo, hi; upk2(acc[r], lo, hi);
                gsm[r * 608 + row] = lo + hi + bias;
            }
        }
    };

    // ---- step-1 matvec: x = ht, h = 0; gate rows (<384) use raw w_ih --------
    auto matvec1 = [&]() {
        const ulonglong2* xg = reinterpret_cast<const ulonglong2*>(xh);
        if (isSplit) {
            // all split rows < 352 < 384: active
            const ulonglong2* w1 = reinterpret_cast<const ulonglong2*>(
                w_ih + (size_t)row * 128 + half * 64);
            ull acc[14];
#pragma unroll
            for (int r = 0; r < 14; r++) acc[r] = 0ull;
#pragma unroll 2
            for (int g16 = 0; g16 < 16; g16++) {
                ulonglong2 w = w1[g16];
#pragma unroll
                for (int r = 0; r < 14; r++) {
                    ulonglong2 xv = xg[r * 32 + g0 + g16];
                    FMA2(acc[r], w.x, xv.x);
                    FMA2(acc[r], w.y, xv.y);
                }
            }
#pragma unroll
            for (int r = 0; r < 14; r++) {
                float lo, hi; upk2(acc[r], lo, hi);
                float part = lo + hi;
                part += __shfl_xor_sync(0xffffffffu, part, 1);
                if (half == 0) gsm[r * 608 + row] = part + bias;
            }
        } else {
            ull acc[14];
#pragma unroll
            for (int r = 0; r < 14; r++) acc[r] = 0ull;
            if (row < 384) {
                const ulonglong2* w1 = reinterpret_cast<const ulonglong2*>(
                    w_ih + (size_t)row * 128);
#pragma unroll 2
                for (int g = 0; g < 32; g++) {
                    ulonglong2 w = w1[g];
#pragma unroll
                    for (int r = 0; r < 14; r++) {
                        ulonglong2 xv = xg[r * 32 + g];
                        FMA2(acc[r], w.x, xv.x);
                        FMA2(acc[r], w.y, xv.y);
                    }
                }
            }
#pragma unroll
            for (int r = 0; r < 14; r++) {
                float lo, hi; upk2(acc[r], lo, hi);
                gsm[r * 608 + row] = lo + hi + bias;
            }
        }
    };

    // ---- GRU gates + state rotation + per-row char maxima -------------------
    auto gatephase = [&](bool step1) -> bool {
        bool changed = false;
        for (int m = tid; m < 14 * HH; m += NT) {
            int r = m >> 7, k = m & 127;
            if (r < nv) {
                float rpre = gsm[r * 608 + k];
                float zpre = gsm[r * 608 + 128 + k];
                float inp  = gsm[r * 608 + 256 + k];
                float hnp  = gsm[r * 608 + 384 + k];
                float rg = __fdividef(1.0f, 1.0f + __expf(-rpre));
                float zg = __fdividef(1.0f, 1.0f + __expf(-zpre));
                float n  = tanhf(inp + rg * hnp);
                int   xi = r * 128 + k;
                float xold = xh[xi];
                float old2 = xp2[xi];
                float hn = step1 ? (1.0f - zg) * n
                                 : (1.0f - zg) * n + zg * xold;
                changed |= (__float_as_int(hn) != __float_as_int(old2));
                xp2[xi] = xold;
                xh[xi]  = hn;
                xl[xi]  = (hn >= 0.f) ? hn : 0.01f * hn;
            }
        }
        if (tid < 56) {
            int r = tid >> 2, q = tid & 3;
            float mx = -3.4e38f;
#pragma unroll
            for (int c = 0; c < 24; c++) mx = fmaxf(mx, gsm[r * 608 + 512 + q * 24 + c]);
            m4[tid] = mx;
        }
        return changed;
    };

    const float THR = (float)(1.0 - 1e-05);

    // pre-step: hn0 = GRU(ht, 0)
    matvec1();
    __syncthreads();
    gatephase(true);
    __syncthreads();

    float cval[2], pval[2];
    int   foff[2];
    int   nslots = 0;
    int   sConv = -1;

    for (int s = 0; s < TSTEPS; s++) {
        matvec();
        __syncthreads();
        bool changed = gatephase(false);
        if (s == 0) changed = true;               // xp2 invalid at s=0
        int cnt = __syncthreads_count(changed ? 1 : 0);

#pragma unroll
        for (int q = 0; q < 2; q++) pval[q] = cval[q];
        nslots = 0;
        for (int m = tid; m < nv * CC; m += NT) {
            int r = m / CC, c = m - r * CC;
            float mx = fmaxf(fmaxf(m4[r * 4 + 0], m4[r * 4 + 1]),
                             fmaxf(m4[r * 4 + 2], m4[r * 4 + 3]));
            float ch = gsm[r * 608 + 512 + c];
            float cn = __fdiv_rn(ch, mx);
            float val = (cn > THR) ? cn : 0.f;
            int off = (base + r) * (TSTEPS * CC) + c;
            out[(size_t)off + (size_t)s * CC] = val;
            if (c == 52 && val == 1.0f && lensm[r] == 0) lensm[r] = s + 1;
            cval[nslots] = val;
            foff[nslots] = off;
            nslots++;
        }

        if (cnt == 0) { sConv = s; break; }
        __syncthreads();
    }

    if (sConv >= 0) {
        // period-2 limit cycle: outputs alternate between steps sConv-1, sConv
        for (int s2 = sConv + 1; s2 < TSTEPS; s2++) {
            bool even = (((s2 - sConv) & 1) == 0);
#pragma unroll
            for (int q = 0; q < 2; q++) {
                if (q < nslots)
                    out[(size_t)foff[q] + (size_t)s2 * CC] = even ? cval[q] : pval[q];
            }
        }
    }

    __syncthreads();
    if (hasLens && tid < nv) {
        int L = lensm[tid];
        out[(size_t)TITLES_ELEMS + base + tid] = (float)(L == 0 ? TSTEPS : L);
    }
}

// ------------------------------- launch -------------------------------------
extern "C" void kernel_launch(void* const* d_in, const int* in_sizes, int n_in,
                              void* d_out, int out_size) {
    const float* img_feat = (const float*)d_in[0];
    const float* lin1_w   = (const float*)d_in[1];
    const float* lin1_b   = (const float*)d_in[2];
    const float* w_ih     = (const float*)d_in[3];
    const float* w_hh     = (const float*)d_in[4];
    const float* b_ih     = (const float*)d_in[5];
    const float* b_hh     = (const float*)d_in[6];
    const float* lin2_w   = (const float*)d_in[7];
    const float* lin2_b   = (const float*)d_in[8];

    cudaFuncSetAttribute(fused_kernel,
                         cudaFuncAttributeMaxDynamicSharedMemorySize, SMEM_TOT);

    int hasLens = (out_size >= TITLES_ELEMS + BB) ? 1 : 0;
    fused_kernel<<<148, 960, SMEM_TOT>>>((float*)d_out, img_feat, lin1_w, lin1_b,
                                         w_ih, w_hh, b_ih, b_hh, lin2_w, lin2_b,
                                         hasLens);
}

// round 17
// speedup vs baseline: 8.9938x; 5.5895x over previous
#include <cuda_runtime.h>
#include <cuda_fp16.h>
#include <cstdint>

// ----------------------------------------------------------------------------
// TitleGenerator, round 16: warp-level HMMA (mma.sync m16n8k16 fp16->f32).
// R14 bug fixed: W blocks are stored [n][k]; the B fragment needs NON-trans
// ldmatrix (thread l holds (n=l>>2, k=(l&3)*2+j), exactly the b0/b1 layout).
// 148 CTAs x 608 threads (19 warps), 400-step rollout.
// Matvec D[16x608] = x[16x128] @ W^T, fp16 double-split 3-term:
//   Whi = fp16(W) -> REGISTERS (ldmatrix'd once from a staging pass)
//   Wlo = fp16(W - Whi) -> SMEM, packed ldmatrix-native layout
//   x -> xhi/xlo fp16 tiles (h and leaky(h) variants), rebuilt per step
//   acc += Whi*xhi + Whi*xlo + Wlo*xhi   (fp32 acc; err ~1e-6)
// Combined-W (x==h after step 1): rows[0,256)=w_ih+w_hh, [256,384)=w_ih_n,
// [384,512)=w_hh_n, [512,608)=lin2 (those use the leaky x tiles).
// Warp w owns W rows 32w..32w+31 (warps 16-18 = lin2 region -> leaky tiles).
// ----------------------------------------------------------------------------

#define HH 128
#define CC 96
#define TSTEPS 400
#define NT 608
#define TITLES_ELEMS 78643200

#define OFF_WLO  0                    // 608x128 fp16, packed 8x8 blocks: 155648
#define OFF_XHH  155648               // x tiles [16x128 fp16] packed: 4096 each
#define OFF_XHL  159744
#define OFF_XLH  163840
#define OFF_XLL  167936
#define OFF_XF   172032               // h state fp32 [14x128]: 7168
#define OFF_GSM  179200               // pre-acts [14x608] f32: 34048
#define OFF_BIAS 213248               // combined bias [608] f32: 2432
#define OFF_M4   215680               // 56 partial maxima: 256
#define OFF_LEN  215936               // 16 ints
#define SMEM_TOT 216064

typedef unsigned long long ull;

__device__ __forceinline__ void upk2(ull v, float& lo, float& hi) {
    asm("mov.b64 {%0, %1}, %2;" : "=f"(lo), "=f"(hi) : "l"(v));
}
#define FMA2(acc, a, b) asm("fma.rn.f32x2 %0, %1, %2, %3;" : "=l"(acc) : "l"(a), "l"(b), "l"(acc))

__device__ __forceinline__ uint32_t smem_u32(const void* p) {
    uint32_t a;
    asm("{ .reg .u64 t; cvta.to.shared.u64 t, %1; cvt.u32.u64 %0, t; }" : "=r"(a) : "l"(p));
    return a;
}
__device__ __forceinline__ void ldmx4(uint32_t* r, uint32_t addr) {
    asm volatile("ldmatrix.sync.aligned.m8n8.x4.shared.b16 {%0,%1,%2,%3}, [%4];"
        : "=r"(r[0]), "=r"(r[1]), "=r"(r[2]), "=r"(r[3]) : "r"(addr));
}
__device__ __forceinline__ void ldmx2(uint32_t* r, uint32_t addr) {
    asm volatile("ldmatrix.sync.aligned.m8n8.x2.shared.b16 {%0,%1}, [%2];"
        : "=r"(r[0]), "=r"(r[1]) : "r"(addr));
}
__device__ __forceinline__ void mma16816(float* d, const uint32_t* a, const uint32_t* b) {
    asm volatile("mma.sync.aligned.m16n8k16.row.col.f32.f16.f16.f32 "
        "{%0,%1,%2,%3}, {%4,%5,%6,%7}, {%8,%9}, {%0,%1,%2,%3};"
        : "+f"(d[0]), "+f"(d[1]), "+f"(d[2]), "+f"(d[3])
        : "r"(a[0]), "r"(a[1]), "r"(a[2]), "r"(a[3]), "r"(b[0]), "r"(b[1]));
}

// packed addr of element (row,k) in a W tensor (8x8 half blocks, ldmatrix-ready)
__device__ __forceinline__ uint32_t wpk(int row, int k) {
    return (uint32_t)((row >> 3) * 2048 + (k >> 4) * 256 + (((k >> 3) & 1) << 7)
                      + ((row & 7) << 4) + ((k & 7) << 1));
}
// packed addr of element (r,k) in a 16x128 x-tile (mat order TL,BL,TR,BR per k16)
__device__ __forceinline__ uint32_t xpk(int r, int k) {
    return (uint32_t)((k >> 4) * 512 + (((r >> 3) + (((k >> 3) & 1) << 1)) << 7)
                      + ((r & 7) << 4) + ((k & 7) << 1));
}
__device__ __forceinline__ float wval(int row, int k, const float* wih,
                                      const float* whh, const float* l2w) {
    if (row < 256) return wih[row * 128 + k] + whh[row * 128 + k];
    if (row < 384) return wih[row * 128 + k];
    if (row < 512) return whh[(row - 128) * 128 + k];
    return l2w[(row - 512) * 128 + k];
}

__global__ __launch_bounds__(608, 1)
void fused_kernel(float* __restrict__ out,
                  const float* __restrict__ img,
                  const float* __restrict__ lin1_w,
                  const float* __restrict__ lin1_b,
                  const float* __restrict__ w_ih,
                  const float* __restrict__ w_hh,
                  const float* __restrict__ b_ih,
                  const float* __restrict__ b_hh,
                  const float* __restrict__ lin2_w,
                  const float* __restrict__ lin2_b,
                  int hasLens) {
    extern __shared__ __align__(16) char smraw[];
    float* xf    = reinterpret_cast<float*>(smraw + OFF_XF);
    float* gsm   = reinterpret_cast<float*>(smraw + OFF_GSM);
    float* bsm   = reinterpret_cast<float*>(smraw + OFF_BIAS);
    float* m4    = reinterpret_cast<float*>(smraw + OFF_M4);
    int*   lensm = reinterpret_cast<int*>(smraw + OFF_LEN);

    const int tid  = threadIdx.x;
    const int bid  = blockIdx.x;
    const int wid  = tid >> 5;
    const int lane = tid & 31;
    int base, nv;
    if (bid < 124) { base = bid * 14; nv = 14; }
    else           { base = 1736 + (bid - 124) * 13; nv = 13; }

    const uint32_t smb   = smem_u32(smraw);
    const uint32_t wlob  = smb + OFF_WLO;
    const int      wr0   = wid * 32;                 // this warp's W row base

    // ---- combined bias, zero buffers ---------------------------------------
    for (int i = tid; i < 608; i += NT) {
        float v;
        if (i < 256)      v = b_ih[i] + b_hh[i];
        else if (i < 384) v = b_ih[i];
        else if (i < 512) v = b_hh[i - 128];
        else              v = lin2_b[i - 512];
        bsm[i] = v;
    }
    for (int i = tid; i < 16384 / 4; i += NT)        // zero all 4 x tiles
        reinterpret_cast<uint32_t*>(smraw + OFF_XHH)[i] = 0;
    for (int m = tid; m < 14 * 128; m += NT) xf[m] = 0.f;
    if (tid < 16) lensm[tid] = 0;

    // ---- stage Whi into wlo region, ldmatrix to registers, then build Wlo --
    __syncthreads();
    {   // each thread owns one W row (608 rows, 608 threads)
        for (int k = 0; k < 128; k++) {
            float w = wval(tid, k, w_ih, w_hh, lin2_w);
            *reinterpret_cast<__half*>(smraw + OFF_WLO + wpk(tid, k)) = __float2half_rn(w);
        }
    }
    __syncthreads();
    uint32_t whi[4][8][2];
    {
        const uint32_t lbase = wlob + (((lane & 15) >> 3) << 7) + ((lane & 7) << 4);
#pragma unroll
        for (int nt = 0; nt < 4; nt++)
#pragma unroll
            for (int kt = 0; kt < 8; kt++)
                ldmx2(whi[nt][kt], lbase + ((wr0 + nt * 8) >> 3) * 2048 + kt * 256);
    }
    __syncthreads();
    {   // overwrite region with Wlo = W - fp16(W)
        for (int k = 0; k < 128; k++) {
            float w = wval(tid, k, w_ih, w_hh, lin2_w);
            __half h = __float2half_rn(w);
            *reinterpret_cast<__half*>(smraw + OFF_WLO + wpk(tid, k)) =
                __float2half_rn(w - __half2float(h));
        }
    }

    // ---- lin1 -> ht (one-time fp32 FFMA; staged in gsm) ---------------------
    {
        const int j  = tid & 127;
        const int ks = tid >> 7;
        ull acc[14];
#pragma unroll
        for (int r = 0; r < 14; r++) acc[r] = 0ull;
        float4*       xs4 = reinterpret_cast<float4*>(gsm);
        const float4* im4 = reinterpret_cast<const float4*>(img);
        const ulonglong2* xs2 = reinterpret_cast<const ulonglong2*>(gsm);
        for (int kc = 0; kc < 16; kc++) {
            __syncthreads();
            for (int m = tid; m < 14 * 64; m += NT) {
                int r = m >> 6, kk4 = m & 63;
                float4 v = make_float4(0.f, 0.f, 0.f, 0.f);
                if (r < nv) v = im4[(size_t)(base + r) * 1024 + kc * 64 + kk4];
                xs4[r * 64 + kk4] = v;
            }
            __syncthreads();
            if (tid < 512) {
                const ulonglong2* wl = reinterpret_cast<const ulonglong2*>(
                    lin1_w + (size_t)j * 4096 + kc * 256 + ks * 64);
#pragma unroll 4
                for (int q = 0; q < 16; q++) {
                    ulonglong2 wv = wl[q];
#pragma unroll
                    for (int r = 0; r < 14; r++) {
                        ulonglong2 xv = xs2[r * 64 + ks * 16 + q];
                        FMA2(acc[r], wv.x, xv.x);
                        FMA2(acc[r], wv.y, xv.y);
                    }
                }
            }
        }
        __syncthreads();
        if (tid < 512) {
#pragma unroll
            for (int r = 0; r < 14; r++) {
                float lo, hi; upk2(acc[r], lo, hi);
                gsm[r * 512 + ks * 128 + j] = lo + hi;
            }
        }
        __syncthreads();
        for (int m = tid; m < 14 * 128; m += NT) {
            int r = m >> 7, jj = m & 127;
            float v = gsm[r * 512 + jj] + gsm[r * 512 + 128 + jj]
                    + gsm[r * 512 + 256 + jj] + gsm[r * 512 + 384 + jj] + lin1_b[jj];
            xf[r * 128 + jj] = (v >= 0.f) ? v : 0.01f * v;
        }
        __syncthreads();
    }

    // ---- gatephase: GRU -> h, write fp16 split x tiles, char maxima ---------
    auto gatephase = [&](bool step1) {
        for (int m = tid; m < nv * HH; m += NT) {
            int r = m >> 7, k = m & 127;
            float rpre = gsm[r * 608 + k];
            float zpre = gsm[r * 608 + 128 + k];
            float inp  = gsm[r * 608 + 256 + k];
            float hnp  = gsm[r * 608 + 384 + k];
            float rg = __fdividef(1.0f, 1.0f + __expf(-rpre));
            float zg = __fdividef(1.0f, 1.0f + __expf(-zpre));
            float n  = tanhf(inp + rg * hnp);
            float xold = xf[r * 128 + k];
            float hn = step1 ? (1.0f - zg) * n : (1.0f - zg) * n + zg * xold;
            xf[r * 128 + k] = hn;
            float lv = (hn >= 0.f) ? hn : 0.01f * hn;
            __half hh = __float2half_rn(hn);
            __half lh = __float2half_rn(lv);
            uint32_t a = xpk(r, k);
            *reinterpret_cast<__half*>(smraw + OFF_XHH + a) = hh;
            *reinterpret_cast<__half*>(smraw + OFF_XHL + a) =
                __float2half_rn(hn - __half2float(hh));
            *reinterpret_cast<__half*>(smraw + OFF_XLH + a) = lh;
            *reinterpret_cast<__half*>(smraw + OFF_XLL + a) =
                __float2half_rn(lv - __half2float(lh));
        }
        if (tid < 56) {
            int r = tid >> 2, q = tid & 3;
            float mx = -3.4e38f;
#pragma unroll
            for (int c = 0; c < 24; c++) mx = fmaxf(mx, gsm[r * 608 + 512 + q * 24 + c]);
            m4[tid] = mx;
        }
    };

    // ---- step-1 matvec (fp32): rows<384 = w_ih . ht; others bias-only -------
    {
        ull acc[14];
#pragma unroll
        for (int r = 0; r < 14; r++) acc[r] = 0ull;
        if (tid < 384) {
            const ulonglong2* wr = reinterpret_cast<const ulonglong2*>(w_ih + (size_t)tid * 128);
            const ulonglong2* xg = reinterpret_cast<const ulonglong2*>(xf);
#pragma unroll 2
            for (int g = 0; g < 32; g++) {
                ulonglong2 wv = wr[g];
#pragma unroll
                for (int r = 0; r < 14; r++) {
                    ulonglong2 xv = xg[r * 32 + g];
                    FMA2(acc[r], wv.x, xv.x);
                    FMA2(acc[r], wv.y, xv.y);
                }
            }
        }
        float b = bsm[tid];
#pragma unroll
        for (int r = 0; r < 14; r++) {
            float lo, hi; upk2(acc[r], lo, hi);
            gsm[r * 608 + tid] = lo + hi + b;
        }
        __syncthreads();
        gatephase(true);
        __syncthreads();
    }

    const float THR = (float)(1.0 - 1e-05);
    // x tile bases for this warp (rows >= 512, i.e. warps 16-18, use leaky)
    const uint32_t xhiB = smb + ((wid < 16) ? OFF_XHH : OFF_XLH);
    const uint32_t xloB = smb + ((wid < 16) ? OFF_XHL : OFF_XLL);
    const uint32_t aoff = ((lane >> 3) << 7) + ((lane & 7) << 4);        // ldmx4 lane addr
    const uint32_t boff = (((lane & 15) >> 3) << 7) + ((lane & 7) << 4); // ldmx2 lane addr
    const int rA = lane >> 2;                 // acc row (d0/d1); d2/d3 at rA+8
    const int c0 = wr0 + (lane & 3) * 2;      // acc col base (+ nt*8)

    for (int s = 0; s < TSTEPS; s++) {
        // ---- HMMA matvec ---------------------------------------------------
        {
            float acc[4][4];
#pragma unroll
            for (int nt = 0; nt < 4; nt++)
#pragma unroll
                for (int q = 0; q < 4; q++) acc[nt][q] = 0.f;
#pragma unroll
            for (int kt = 0; kt < 8; kt++) {
                uint32_t ah[4], al[4], bl[2];
                ldmx4(ah, xhiB + kt * 512 + aoff);
                ldmx4(al, xloB + kt * 512 + aoff);
#pragma unroll
                for (int nt = 0; nt < 4; nt++) {
                    ldmx2(bl, wlob + ((wr0 + nt * 8) >> 3) * 2048 + kt * 256 + boff);
                    mma16816(acc[nt], ah, whi[nt][kt]);
                    mma16816(acc[nt], al, whi[nt][kt]);
                    mma16816(acc[nt], ah, bl);
                }
            }
#pragma unroll
            for (int nt = 0; nt < 4; nt++) {
                int col = c0 + nt * 8;
                float b0 = bsm[col], b1 = bsm[col + 1];
                *reinterpret_cast<float2*>(&gsm[rA * 608 + col]) =
                    make_float2(acc[nt][0] + b0, acc[nt][1] + b1);
                if (rA < 6)
                    *reinterpret_cast<float2*>(&gsm[(rA + 8) * 608 + col]) =
                        make_float2(acc[nt][2] + b0, acc[nt][3] + b1);
            }
        }
        __syncthreads();

        gatephase(false);
        __syncthreads();

        // ---- output: chars_s from lin2 rows + maxima -----------------------
        for (int m = tid; m < nv * CC; m += NT) {
            int r = m / CC, c = m - r * CC;
            float mx = fmaxf(fmaxf(m4[r * 4 + 0], m4[r * 4 + 1]),
                             fmaxf(m4[r * 4 + 2], m4[r * 4 + 3]));
            float ch = gsm[r * 608 + 512 + c];
            float cn = __fdiv_rn(ch, mx);
            float val = (cn > THR) ? cn : 0.f;
            out[(size_t)(base + r) * (TSTEPS * CC) + (size_t)s * CC + c] = val;
            if (c == 52 && val == 1.0f && lensm[r] == 0) lensm[r] = s + 1;
        }
        __syncthreads();
    }

    if (hasLens && tid < nv) {
        int L = lensm[tid];
        out[(size_t)TITLES_ELEMS + base + tid] = (float)(L == 0 ? TSTEPS : L);
    }
}

// ------------------------------- launch -------------------------------------
extern "C" void kernel_launch(void* const* d_in, const int* in_sizes, int n_in,
                              void* d_out, int out_size) {
    const float* img_feat = (const float*)d_in[0];
    const float* lin1_w   = (const float*)d_in[1];
    const float* lin1_b   = (const float*)d_in[2];
    const float* w_ih     = (const float*)d_in[3];
    const float* w_hh     = (const float*)d_in[4];
    const float* b_ih     = (const float*)d_in[5];
    const float* b_hh     = (const float*)d_in[6];
    const float* lin2_w   = (const float*)d_in[7];
    const float* lin2_b   = (const float*)d_in[8];

    cudaFuncSetAttribute(fused_kernel,
                         cudaFuncAttributeMaxDynamicSharedMemorySize, SMEM_TOT);

    int hasLens = (out_size >= TITLES_ELEMS + 2048) ? 1 : 0;
    fused_kernel<<<148, 608, SMEM_TOT>>>((float*)d_out, img_feat, lin1_w, lin1_b,
                                         w_ih, w_hh, b_ih, b_hh, lin2_w, lin2_b,
                                         hasLens);
}